// round 5
// baseline (speedup 1.0000x reference)
#include <cuda_runtime.h>
#include <math.h>

#define BATCH 200000
#define HALF  (BATCH / 2)
#define TBS 256
#define NBLK ((HALF + TBS - 1) / TBS)   // 391
#define MAX_ITERS 10
#define RTOL 1e-5f
#define ATOL 1e-5f

typedef unsigned long long ull;

// ---------------------------------------------------------------------------
// Packed parameter set (params duplicated across f32x2 lanes; U negated)
// ---------------------------------------------------------------------------
struct __align__(16) ParSet {
    float4 wv[64];   // {W0,W0,W1,W1}
    float4 bw[64];   // {b,b,wu,wu}
    float4 uv[64];   // {-U0,-U0,-U1,-U1}
    float  sumwu64;  // (sum wu)/64
    float  pad[3];
};                   // 3088 bytes = 193 float4

struct Ctl { float t, dt, last_t, h0, d1; int active, cur; };
__device__ Ctl    g_ctl;
__device__ ParSet g_par[5];
__device__ double g_part[2][NBLK];
__device__ int    g_cnt[MAX_ITERS + 4];     // zero-init; self-resetting

__device__ float2 g_yz[2][BATCH];
__device__ float  g_yl[2][BATCH];
__device__ float2 g_fz[2][BATCH];
__device__ float  g_fl[2][BATCH];
__device__ float4 g_ic[2][5][BATCH];

__constant__ float c_ALPHA[5] = { 0.2f, 0.3f, 0.8f, (float)(8.0/9.0), 1.0f };

// ---------------------------------------------------------------------------
// f32x2 helpers
// ---------------------------------------------------------------------------
__device__ __forceinline__ ull pk2(float a, float b) {
    ull r;
    asm("mov.b64 %0, {%1,%2};" : "=l"(r)
        : "r"(__float_as_uint(a)), "r"(__float_as_uint(b)));
    return r;
}
__device__ __forceinline__ void upk2(ull p, float& a, float& b) {
    unsigned ua, ub;
    asm("mov.b64 {%0,%1}, %2;" : "=r"(ua), "=r"(ub) : "l"(p));
    a = __uint_as_float(ua); b = __uint_as_float(ub);
}
__device__ __forceinline__ ull f2fma(ull a, ull b, ull c) {
    ull d;
    asm("fma.rn.f32x2 %0, %1, %2, %3;" : "=l"(d) : "l"(a), "l"(b), "l"(c));
    return d;
}
__device__ __forceinline__ ull f2mul(ull a, ull b) {
    ull d;
    asm("mul.rn.f32x2 %0, %1, %2;" : "=l"(d) : "l"(a), "l"(b));
    return d;
}
__device__ __forceinline__ ull f2dup(float a) { return pk2(a, a); }

__device__ __forceinline__ float tanh_fast(float x) {
    float y;
    asm("tanh.approx.f32 %0, %1;" : "=f"(y) : "f"(x));
    return y;
}

// ---------------------------------------------------------------------------
// packed reverse-ODE RHS for an (A,B) element pair
// ---------------------------------------------------------------------------
__device__ __forceinline__ void rhs_pack(const ParSet* __restrict__ P,
                                         ull z0p, ull z1p,
                                         ull& f0p, ull& f1p, ull& flp) {
    const ulonglong2* __restrict__ W  = reinterpret_cast<const ulonglong2*>(P->wv);
    const ulonglong2* __restrict__ BW = reinterpret_cast<const ulonglong2*>(P->bw);
    const ulonglong2* __restrict__ UV = reinterpret_cast<const ulonglong2*>(P->uv);
    ull a0 = 0ull, a1 = 0ull, tr = 0ull;
    #pragma unroll 16
    for (int i = 0; i < 64; i++) {
        ulonglong2 w  = W[i];
        ulonglong2 bw = BW[i];
        ulonglong2 uv = UV[i];
        ull pre = f2fma(z0p, w.x, f2fma(z1p, w.y, bw.x));
        float pa, pb; upk2(pre, pa, pb);
        ull hp = pk2(tanh_fast(pa), tanh_fast(pb));
        a0 = f2fma(hp, uv.x, a0);
        a1 = f2fma(hp, uv.y, a1);
        tr = f2fma(f2mul(hp, hp), bw.y, tr);
    }
    const ull c64  = f2dup(1.0f / 64.0f);
    const ull nc64 = f2dup(-1.0f / 64.0f);
    f0p = f2mul(a0, c64);                       // U stored negated -> sign built in
    f1p = f2mul(a1, c64);
    flp = f2fma(tr, nc64, f2dup(P->sumwu64));   // (sum wu - sum h^2 wu)/64
}

// ---------------------------------------------------------------------------
// hypernet for one time value, executed by one full 256-thread block
// ---------------------------------------------------------------------------
__device__ void hyper_block(float t, ParSet* dst,
                            const float* __restrict__ fc1_w, const float* __restrict__ fc1_b,
                            const float* __restrict__ fc2_w, const float* __restrict__ fc2_b,
                            const float* __restrict__ fc3_w, const float* __restrict__ fc3_b,
                            float* s1, float* s2, float* s3) {
    const int tid = threadIdx.x;
    if (tid < 64)
        s1[tid] = tanhf(fmaf(fc1_w[tid], t, fc1_b[tid]));
    __syncthreads();
    if (tid < 64) {
        float acc = fc2_b[tid];
        const float* row = fc2_w + tid * 64;
        #pragma unroll 8
        for (int k = 0; k < 64; k++) acc = fmaf(row[k], s1[k], acc);
        s2[tid] = tanhf(acc);
    }
    __syncthreads();
    for (int r = tid; r < 448; r += TBS) {
        float acc = fc3_b[r];
        const float* row = fc3_w + r * 64;
        #pragma unroll 8
        for (int k = 0; k < 64; k++) acc = fmaf(row[k], s2[k], acc);
        s3[r] = acc;
    }
    __syncthreads();
    if (tid < 64) {
        float W0 = s3[2*tid], W1 = s3[2*tid+1];
        float U0 = s3[128+2*tid], U1 = s3[128+2*tid+1];
        float G0 = s3[256+2*tid], G1 = s3[256+2*tid+1];
        float b  = s3[384+tid];
        U0 *= 1.0f / (1.0f + expf(-G0));
        U1 *= 1.0f / (1.0f + expf(-G1));
        float wu = W0 * U0 + W1 * U1;
        dst->wv[tid] = make_float4(W0, W0, W1, W1);
        dst->bw[tid] = make_float4(b, b, wu, wu);
        dst->uv[tid] = make_float4(-U0, -U0, -U1, -U1);
        s1[tid] = wu;
    }
    __syncthreads();
    for (int s = 32; s > 0; s >>= 1) {
        if (tid < s) s1[tid] += s1[tid + s];
        __syncthreads();
    }
    if (tid == 0) dst->sumwu64 = s1[0] * (1.0f / 64.0f);
    __syncthreads();
}

__device__ __forceinline__ double block_reduce(double v, double* sd) {
    int tid = threadIdx.x;
    sd[tid] = v;
    __syncthreads();
    for (int s = TBS / 2; s > 0; s >>= 1) {
        if (tid < s) sd[tid] += sd[tid + s];
        __syncthreads();
    }
    double r = sd[0];
    __syncthreads();
    return r;
}

__device__ __forceinline__ bool elect_last_block(int slot) {
    __threadfence();
    __shared__ int isLast;
    if (threadIdx.x == 0) {
        int c = atomicAdd(&g_cnt[slot], 1);
        isLast = (c == (int)gridDim.x - 1);
    }
    __syncthreads();
    return isLast != 0;
}

// ---------------------------------------------------------------------------
// hyper0: initial params at t = 1 (s = 0)
// ---------------------------------------------------------------------------
__global__ __launch_bounds__(TBS)
void hyper0_kernel(const float* fc1_w, const float* fc1_b,
                   const float* fc2_w, const float* fc2_b,
                   const float* fc3_w, const float* fc3_b) {
    __shared__ float s1[64], s2[64], s3[448];
    hyper_block(1.0f, &g_par[0], fc1_w, fc1_b, fc2_w, fc2_b, fc3_w, fc3_b, s1, s2, s3);
}

// ---------------------------------------------------------------------------
// f0: f(y0,0) + d0,d1 norms; tail: h0 + hypernet(t = 1-h0)
// ---------------------------------------------------------------------------
__global__ __launch_bounds__(TBS)
void f0_kernel(const float* __restrict__ x, const float* __restrict__ lp_in,
               const float* fc1_w, const float* fc1_b,
               const float* fc2_w, const float* fc2_b,
               const float* fc3_w, const float* fc3_b) {
    __shared__ ParSet sp;
    __shared__ double sd[TBS];
    __shared__ float s1[64], s2[64], s3[448];
    __shared__ float sb[1];
    for (int j = threadIdx.x; j < 193; j += TBS)
        reinterpret_cast<float4*>(&sp)[j] = reinterpret_cast<const float4*>(&g_par[0])[j];
    __syncthreads();

    const int gid = blockIdx.x * TBS + threadIdx.x;
    double n0 = 0.0, n1 = 0.0;
    if (gid < HALF) {
        float2 ya = reinterpret_cast<const float2*>(x)[gid];
        float2 yb = reinterpret_cast<const float2*>(x)[gid + HALF];
        float  la = lp_in[gid];
        float  lb = lp_in[gid + HALF];
        ull f0p, f1p, flp;
        rhs_pack(&sp, pk2(ya.x, yb.x), pk2(ya.y, yb.y), f0p, f1p, flp);
        float fa0, fb0, fa1, fb1, fal, fbl;
        upk2(f0p, fa0, fb0); upk2(f1p, fa1, fb1); upk2(flp, fal, fbl);

        g_yz[0][gid] = ya;          g_yz[0][gid + HALF] = yb;
        g_yl[0][gid] = la;          g_yl[0][gid + HALF] = lb;
        g_fz[0][gid] = make_float2(fa0, fa1);
        g_fz[0][gid + HALF] = make_float2(fb0, fb1);
        g_fl[0][gid] = fal;         g_fl[0][gid + HALF] = fbl;

        float sc0 = ATOL + RTOL * fabsf(ya.x);
        float sc1 = ATOL + RTOL * fabsf(ya.y);
        float scl = ATOL + RTOL * fabsf(la);
        float a = ya.x/sc0, b = ya.y/sc1, c = la/scl;
        n0 += (double)a*a + (double)b*b + (double)c*c;
        a = fa0/sc0; b = fa1/sc1; c = fal/scl;
        n1 += (double)a*a + (double)b*b + (double)c*c;
        sc0 = ATOL + RTOL * fabsf(yb.x);
        sc1 = ATOL + RTOL * fabsf(yb.y);
        scl = ATOL + RTOL * fabsf(lb);
        a = yb.x/sc0; b = yb.y/sc1; c = lb/scl;
        n0 += (double)a*a + (double)b*b + (double)c*c;
        a = fb0/sc0; b = fb1/sc1; c = fbl/scl;
        n1 += (double)a*a + (double)b*b + (double)c*c;
    }
    double t0 = block_reduce(n0, sd);
    double t1 = block_reduce(n1, sd);
    if (threadIdx.x == 0) { g_part[0][blockIdx.x] = t0; g_part[1][blockIdx.x] = t1; }

    if (elect_last_block(0)) {
        double a0 = 0.0, a1 = 0.0;
        for (int i = threadIdx.x; i < NBLK; i += TBS) { a0 += g_part[0][i]; a1 += g_part[1][i]; }
        double r0 = block_reduce(a0, sd);
        double r1 = block_reduce(a1, sd);
        if (threadIdx.x == 0) {
            float d0 = (float)sqrt(r0);
            float d1 = (float)sqrt(r1);
            float h0 = (d0 < 1e-5f || d1 < 1e-5f) ? 1e-6f : 0.01f * d0 / d1;
            g_ctl.h0 = h0;  g_ctl.d1 = d1;
            g_cnt[0] = 0;
            sb[0] = h0;
        }
        __syncthreads();
        hyper_block(1.0f - sb[0], &g_par[0],
                    fc1_w, fc1_b, fc2_w, fc2_b, fc3_w, fc3_b, s1, s2, s3);
    }
}

// ---------------------------------------------------------------------------
// f1: f(y0+h0*f0, h0) + d2 norm; tail: dt, ctl init, hypernet x5
// ---------------------------------------------------------------------------
__global__ __launch_bounds__(TBS)
void f1_kernel(const float* fc1_w, const float* fc1_b,
               const float* fc2_w, const float* fc2_b,
               const float* fc3_w, const float* fc3_b) {
    __shared__ ParSet sp;
    __shared__ double sd[TBS];
    __shared__ float s1[64], s2[64], s3[448];
    __shared__ float sb[1];
    for (int j = threadIdx.x; j < 193; j += TBS)
        reinterpret_cast<float4*>(&sp)[j] = reinterpret_cast<const float4*>(&g_par[0])[j];
    __syncthreads();

    const int gid = blockIdx.x * TBS + threadIdx.x;
    const float h0 = g_ctl.h0;
    double n2 = 0.0;
    if (gid < HALF) {
        float2 ya = g_yz[0][gid];          float la = g_yl[0][gid];
        float2 yb = g_yz[0][gid + HALF];   float lb = g_yl[0][gid + HALF];
        float2 fa = g_fz[0][gid];          float fla = g_fl[0][gid];
        float2 fb = g_fz[0][gid + HALF];   float flb = g_fl[0][gid + HALF];
        ull n0p, n1p, nlp;
        rhs_pack(&sp,
                 pk2(fmaf(h0, fa.x, ya.x), fmaf(h0, fb.x, yb.x)),
                 pk2(fmaf(h0, fa.y, ya.y), fmaf(h0, fb.y, yb.y)),
                 n0p, n1p, nlp);
        float na0, nb0, na1, nb1, nal, nbl;
        upk2(n0p, na0, nb0); upk2(n1p, na1, nb1); upk2(nlp, nal, nbl);

        float sc0 = ATOL + RTOL * fabsf(ya.x);
        float sc1 = ATOL + RTOL * fabsf(ya.y);
        float scl = ATOL + RTOL * fabsf(la);
        float a = (na0 - fa.x)/sc0, b = (na1 - fa.y)/sc1, c = (nal - fla)/scl;
        n2 += (double)a*a + (double)b*b + (double)c*c;
        sc0 = ATOL + RTOL * fabsf(yb.x);
        sc1 = ATOL + RTOL * fabsf(yb.y);
        scl = ATOL + RTOL * fabsf(lb);
        a = (nb0 - fb.x)/sc0; b = (nb1 - fb.y)/sc1; c = (nbl - flb)/scl;
        n2 += (double)a*a + (double)b*b + (double)c*c;
    }
    double t2 = block_reduce(n2, sd);
    if (threadIdx.x == 0) g_part[0][blockIdx.x] = t2;

    if (elect_last_block(1)) {
        double a0 = 0.0;
        for (int i = threadIdx.x; i < NBLK; i += TBS) a0 += g_part[0][i];
        double tot = block_reduce(a0, sd);
        if (threadIdx.x == 0) {
            float d1 = g_ctl.d1;
            float d2 = (float)sqrt(tot) / h0;
            float h1 = (d1 <= 1e-15f && d2 <= 1e-15f)
                     ? fmaxf(1e-6f, h0 * 1e-3f)
                     : powf(0.01f / fmaxf(d1, d2), 0.2f);
            float dt = fminf(100.0f * h0, h1);
            g_ctl.t = 0.0f;  g_ctl.last_t = 0.0f;  g_ctl.dt = dt;
            g_ctl.active = 1;  g_ctl.cur = 0;
            g_cnt[1] = 0;
            sb[0] = dt;
        }
        __syncthreads();
        float dt = sb[0];
        #pragma unroll
        for (int i = 0; i < 5; i++)
            hyper_block(1.0f - dt * c_ALPHA[i], &g_par[i],
                        fc1_w, fc1_b, fc2_w, fc2_b, fc3_w, fc3_b, s1, s2, s3);
    }
}

// ---------------------------------------------------------------------------
// rk: one dopri5 step (packed), tail: controller + hypernet x5
// ---------------------------------------------------------------------------
__global__ __launch_bounds__(TBS, 3)
void rk_kernel(int slot,
               const float* fc1_w, const float* fc1_b,
               const float* fc2_w, const float* fc2_b,
               const float* fc3_w, const float* fc3_b) {
    if (!g_ctl.active) return;
    __shared__ ParSet sp[5];
    __shared__ double sd[TBS];
    __shared__ float s1[64], s2[64], s3[448];
    __shared__ float sb[3];
    for (int j = threadIdx.x; j < 5 * 193; j += TBS)
        reinterpret_cast<float4*>(sp)[j] = reinterpret_cast<const float4*>(g_par)[j];
    __syncthreads();

    const float B1 = (float)(1.0/5.0);
    const float B20 = (float)(3.0/40.0), B21 = (float)(9.0/40.0);
    const float B30 = (float)(44.0/45.0), B31 = (float)(-56.0/15.0), B32 = (float)(32.0/9.0);
    const float B40 = (float)(19372.0/6561.0), B41 = (float)(-25360.0/2187.0),
                B42 = (float)(64448.0/6561.0), B43 = (float)(-212.0/729.0);
    const float B50 = (float)(9017.0/3168.0), B51 = (float)(-355.0/33.0),
                B52 = (float)(46732.0/5247.0), B53 = (float)(49.0/176.0),
                B54 = (float)(-5103.0/18656.0);
    const float CS0 = (float)(35.0/384.0), CS2 = (float)(500.0/1113.0),
                CS3 = (float)(125.0/192.0), CS4 = (float)(-2187.0/6784.0),
                CS5 = (float)(11.0/84.0);
    const float CE[7] = {
        (float)(35.0/384.0 - 1951.0/21600.0), 0.0f,
        (float)(500.0/1113.0 - 22642.0/50085.0),
        (float)(125.0/192.0 - 451.0/720.0),
        (float)(-2187.0/6784.0 + 12231.0/42400.0),
        (float)(11.0/84.0 - 649.0/6300.0),
        (float)(-1.0/60.0) };
    const float CM[7] = {
        (float)(6025192743.0/30085553152.0/2.0), 0.0f,
        (float)(51252292925.0/65400821598.0/2.0),
        (float)(-2691868925.0/45128329728.0/2.0),
        (float)(187940372067.0/1594534317056.0/2.0),
        (float)(-1776094331.0/19743644256.0/2.0),
        (float)(11237099.0/235043384.0/2.0) };

    const int gid = blockIdx.x * TBS + threadIdx.x;
    const int cur = g_ctl.cur;
    const int nc = cur ^ 1;
    const float dt = g_ctl.dt;
    double esum = 0.0;

    if (gid < HALF) {
        const int gA = gid, gB = gid + HALF;
        float2 yzA = g_yz[cur][gA];  float ylA = g_yl[cur][gA];
        float2 yzB = g_yz[cur][gB];  float ylB = g_yl[cur][gB];
        float2 fzA = g_fz[cur][gA];  float flA = g_fl[cur][gA];
        float2 fzB = g_fz[cur][gB];  float flB = g_fl[cur][gB];

        ull y0p = pk2(yzA.x, yzB.x);
        ull y1p = pk2(yzA.y, yzB.y);
        ull ylp = pk2(ylA, ylB);
        ull dtp = f2dup(dt);

        ull k0[7], k1[7], kl[7];
        k0[0] = pk2(fzA.x, fzB.x);
        k1[0] = pk2(fzA.y, fzB.y);
        kl[0] = pk2(flA, flB);

        // stage 1
        rhs_pack(&sp[0], f2fma(dtp, f2mul(f2dup(B1), k0[0]), y0p),
                          f2fma(dtp, f2mul(f2dup(B1), k1[0]), y1p),
                 k0[1], k1[1], kl[1]);
        // stage 2
        {
            ull a0 = f2fma(f2dup(B21), k0[1], f2mul(f2dup(B20), k0[0]));
            ull a1 = f2fma(f2dup(B21), k1[1], f2mul(f2dup(B20), k1[0]));
            rhs_pack(&sp[1], f2fma(dtp, a0, y0p), f2fma(dtp, a1, y1p),
                     k0[2], k1[2], kl[2]);
        }
        // stage 3
        {
            ull a0 = f2mul(f2dup(B30), k0[0]);
            a0 = f2fma(f2dup(B31), k0[1], a0);
            a0 = f2fma(f2dup(B32), k0[2], a0);
            ull a1 = f2mul(f2dup(B30), k1[0]);
            a1 = f2fma(f2dup(B31), k1[1], a1);
            a1 = f2fma(f2dup(B32), k1[2], a1);
            rhs_pack(&sp[2], f2fma(dtp, a0, y0p), f2fma(dtp, a1, y1p),
                     k0[3], k1[3], kl[3]);
        }
        // stage 4
        {
            ull a0 = f2mul(f2dup(B40), k0[0]);
            a0 = f2fma(f2dup(B41), k0[1], a0);
            a0 = f2fma(f2dup(B42), k0[2], a0);
            a0 = f2fma(f2dup(B43), k0[3], a0);
            ull a1 = f2mul(f2dup(B40), k1[0]);
            a1 = f2fma(f2dup(B41), k1[1], a1);
            a1 = f2fma(f2dup(B42), k1[2], a1);
            a1 = f2fma(f2dup(B43), k1[3], a1);
            rhs_pack(&sp[3], f2fma(dtp, a0, y0p), f2fma(dtp, a1, y1p),
                     k0[4], k1[4], kl[4]);
        }
        // stage 5
        {
            ull a0 = f2mul(f2dup(B50), k0[0]);
            a0 = f2fma(f2dup(B51), k0[1], a0);
            a0 = f2fma(f2dup(B52), k0[2], a0);
            a0 = f2fma(f2dup(B53), k0[3], a0);
            a0 = f2fma(f2dup(B54), k0[4], a0);
            ull a1 = f2mul(f2dup(B50), k1[0]);
            a1 = f2fma(f2dup(B51), k1[1], a1);
            a1 = f2fma(f2dup(B52), k1[2], a1);
            a1 = f2fma(f2dup(B53), k1[3], a1);
            a1 = f2fma(f2dup(B54), k1[4], a1);
            rhs_pack(&sp[4], f2fma(dtp, a0, y0p), f2fma(dtp, a1, y1p),
                     k0[5], k1[5], kl[5]);
        }
        // solution combination (c_sol == stage-6 row)
        ull s0 = f2mul(f2dup(CS0), k0[0]);
        s0 = f2fma(f2dup(CS2), k0[2], s0);
        s0 = f2fma(f2dup(CS3), k0[3], s0);
        s0 = f2fma(f2dup(CS4), k0[4], s0);
        s0 = f2fma(f2dup(CS5), k0[5], s0);
        ull sol1 = f2mul(f2dup(CS0), k1[0]);
        sol1 = f2fma(f2dup(CS2), k1[2], sol1);
        sol1 = f2fma(f2dup(CS3), k1[3], sol1);
        sol1 = f2fma(f2dup(CS4), k1[4], sol1);
        sol1 = f2fma(f2dup(CS5), k1[5], sol1);
        ull soll = f2mul(f2dup(CS0), kl[0]);
        soll = f2fma(f2dup(CS2), kl[2], soll);
        soll = f2fma(f2dup(CS3), kl[3], soll);
        soll = f2fma(f2dup(CS4), kl[4], soll);
        soll = f2fma(f2dup(CS5), kl[5], soll);

        ull ny0 = f2fma(dtp, s0, y0p);
        ull ny1 = f2fma(dtp, sol1, y1p);
        ull nyl = f2fma(dtp, soll, ylp);

        // stage 6 (FSAL) at the new point
        rhs_pack(&sp[4], ny0, ny1, k0[6], k1[6], kl[6]);

        // error & midpoint combinations over 7 k's
        ull e0 = 0ull, e1 = 0ull, el = 0ull, m0 = 0ull, m1 = 0ull, ml = 0ull;
        #pragma unroll
        for (int j = 0; j < 7; j++) {
            ull ce = f2dup(CE[j]), cm = f2dup(CM[j]);
            e0 = f2fma(ce, k0[j], e0);  e1 = f2fma(ce, k1[j], e1);
            el = f2fma(ce, kl[j], el);
            m0 = f2fma(cm, k0[j], m0);  m1 = f2fma(cm, k1[j], m1);
            ml = f2fma(cm, kl[j], ml);
        }
        e0 = f2mul(dtp, e0);  e1 = f2mul(dtp, e1);  el = f2mul(dtp, el);
        ull ym0 = f2fma(dtp, m0, y0p);
        ull ym1 = f2fma(dtp, m1, y1p);
        ull yml = f2fma(dtp, ml, ylp);

        // unpack for error ratios and stores
        float yA0, yB0, yA1, yB1, yAl, yBl;
        upk2(ny0, yA0, yB0); upk2(ny1, yA1, yB1); upk2(nyl, yAl, yBl);
        float eA0, eB0, eA1, eB1, eAl, eBl;
        upk2(e0, eA0, eB0); upk2(e1, eA1, eB1); upk2(el, eAl, eBl);

        {
            float t0 = ATOL + RTOL * fmaxf(fabsf(yzA.x), fabsf(yA0));
            float t1 = ATOL + RTOL * fmaxf(fabsf(yzA.y), fabsf(yA1));
            float tl = ATOL + RTOL * fmaxf(fabsf(ylA),   fabsf(yAl));
            float r0 = eA0/t0, r1 = eA1/t1, rl = eAl/tl;
            esum += (double)r0*r0 + (double)r1*r1 + (double)rl*rl;
            t0 = ATOL + RTOL * fmaxf(fabsf(yzB.x), fabsf(yB0));
            t1 = ATOL + RTOL * fmaxf(fabsf(yzB.y), fabsf(yB1));
            tl = ATOL + RTOL * fmaxf(fabsf(ylB),   fabsf(yBl));
            r0 = eB0/t0; r1 = eB1/t1; rl = eBl/tl;
            esum += (double)r0*r0 + (double)r1*r1 + (double)rl*rl;
        }

        g_yz[nc][gA] = make_float2(yA0, yA1);  g_yl[nc][gA] = yAl;
        g_yz[nc][gB] = make_float2(yB0, yB1);  g_yl[nc][gB] = yBl;
        {
            float fA0, fB0, fA1, fB1, fAl, fBl;
            upk2(k0[6], fA0, fB0); upk2(k1[6], fA1, fB1); upk2(kl[6], fAl, fBl);
            g_fz[nc][gA] = make_float2(fA0, fA1);  g_fl[nc][gA] = fAl;
            g_fz[nc][gB] = make_float2(fB0, fB1);  g_fl[nc][gB] = fBl;
        }

        // interp coefficients (packed), then per-element stores
        ull d0c[3] = { f2mul(dtp, k0[0]), f2mul(dtp, k1[0]), f2mul(dtp, kl[0]) };
        ull d1c[3] = { f2mul(dtp, k0[6]), f2mul(dtp, k1[6]), f2mul(dtp, kl[6]) };
        ull yc0[3] = { y0p, y1p, ylp };
        ull yc1[3] = { ny0, ny1, nyl };
        ull ycm[3] = { ym0, ym1, yml };
        float Av[3][2], Bv[3][2], Cv[3][2], Dv[3][2], Ev[3][2];
        #pragma unroll
        for (int c = 0; c < 3; c++) {
            ull A = f2fma(f2dup(-2.f), d0c[c], f2mul(f2dup(2.f), d1c[c]));
            A = f2fma(f2dup(-8.f), yc0[c], A);
            A = f2fma(f2dup(-8.f), yc1[c], A);
            A = f2fma(f2dup(16.f), ycm[c], A);
            ull Bc = f2fma(f2dup(5.f), d0c[c], f2mul(f2dup(-3.f), d1c[c]));
            Bc = f2fma(f2dup(18.f), yc0[c], Bc);
            Bc = f2fma(f2dup(14.f), yc1[c], Bc);
            Bc = f2fma(f2dup(-32.f), ycm[c], Bc);
            ull Cc = f2fma(f2dup(-4.f), d0c[c], d1c[c]);
            Cc = f2fma(f2dup(-11.f), yc0[c], Cc);
            Cc = f2fma(f2dup(-5.f), yc1[c], Cc);
            Cc = f2fma(f2dup(16.f), ycm[c], Cc);
            upk2(A,  Av[c][0], Av[c][1]);
            upk2(Bc, Bv[c][0], Bv[c][1]);
            upk2(Cc, Cv[c][0], Cv[c][1]);
            upk2(d0c[c], Dv[c][0], Dv[c][1]);
            upk2(yc0[c], Ev[c][0], Ev[c][1]);
        }
        g_ic[nc][0][gA] = make_float4(Av[0][0], Av[1][0], Av[2][0], 0.f);
        g_ic[nc][1][gA] = make_float4(Bv[0][0], Bv[1][0], Bv[2][0], 0.f);
        g_ic[nc][2][gA] = make_float4(Cv[0][0], Cv[1][0], Cv[2][0], 0.f);
        g_ic[nc][3][gA] = make_float4(Dv[0][0], Dv[1][0], Dv[2][0], 0.f);
        g_ic[nc][4][gA] = make_float4(Ev[0][0], Ev[1][0], Ev[2][0], 0.f);
        g_ic[nc][0][gB] = make_float4(Av[0][1], Av[1][1], Av[2][1], 0.f);
        g_ic[nc][1][gB] = make_float4(Bv[0][1], Bv[1][1], Bv[2][1], 0.f);
        g_ic[nc][2][gB] = make_float4(Cv[0][1], Cv[1][1], Cv[2][1], 0.f);
        g_ic[nc][3][gB] = make_float4(Dv[0][1], Dv[1][1], Dv[2][1], 0.f);
        g_ic[nc][4][gB] = make_float4(Ev[0][1], Ev[1][1], Ev[2][1], 0.f);
    }

    double tot = block_reduce(esum, sd);
    if (threadIdx.x == 0) g_part[0][blockIdx.x] = tot;

    if (elect_last_block(slot)) {
        double a0 = 0.0;
        for (int i = threadIdx.x; i < NBLK; i += TBS) a0 += g_part[0][i];
        double t2 = block_reduce(a0, sd);
        if (threadIdx.x == 0) {
            float r = (float)sqrt(t2 / (3.0 * (double)BATCH));
            float dtc = g_ctl.dt;
            float dfac = (r < 1.0f) ? 1.0f : 0.2f;
            float factor = fminf(10.0f, fmaxf(powf(r, -0.2f) * 0.9f, dfac));
            float dt_new = (r == 0.0f) ? dtc * 10.0f : dtc * factor;
            if (r <= 1.0f) {
                g_ctl.last_t = g_ctl.t;
                g_ctl.t += dtc;
                g_ctl.cur ^= 1;
            }
            g_ctl.dt = dt_new;
            int act = (g_ctl.t < 1.0f);
            g_ctl.active = act;
            g_cnt[slot] = 0;
            sb[0] = g_ctl.t;  sb[1] = dt_new;  sb[2] = (float)act;
        }
        __syncthreads();
        if (sb[2] != 0.0f) {
            float tcur = sb[0], dtn = sb[1];
            #pragma unroll
            for (int i = 0; i < 5; i++)
                hyper_block(1.0f - fmaf(dtn, c_ALPHA[i], tcur), &g_par[i],
                            fc1_w, fc1_b, fc2_w, fc2_b, fc3_w, fc3_b, s1, s2, s3);
        }
    }
}

// ---------------------------------------------------------------------------
// output: polyval of last accepted step's quartic
// ---------------------------------------------------------------------------
__global__ __launch_bounds__(TBS)
void out_kernel(float* __restrict__ out) {
    int gid = blockIdx.x * TBS + threadIdx.x;
    if (gid >= BATCH) return;
    const int cur = g_ctl.cur;
    const float xr = (1.0f - g_ctl.last_t) / (g_ctl.t - g_ctl.last_t);
    float4 A  = g_ic[cur][0][gid];
    float4 Bc = g_ic[cur][1][gid];
    float4 C  = g_ic[cur][2][gid];
    float4 D  = g_ic[cur][3][gid];
    float4 E  = g_ic[cur][4][gid];
    float z0 = fmaf(fmaf(fmaf(fmaf(A.x, xr, Bc.x), xr, C.x), xr, D.x), xr, E.x);
    float z1 = fmaf(fmaf(fmaf(fmaf(A.y, xr, Bc.y), xr, C.y), xr, D.y), xr, E.y);
    float lp = fmaf(fmaf(fmaf(fmaf(A.z, xr, Bc.z), xr, C.z), xr, D.z), xr, E.z);
    reinterpret_cast<float2*>(out)[gid] = make_float2(z0, z1);
    out[2 * BATCH + gid] = lp;
}

// ---------------------------------------------------------------------------
extern "C" void kernel_launch(void* const* d_in, const int* in_sizes, int n_in,
                              void* d_out, int out_size) {
    const float* x     = (const float*)d_in[0];
    const float* lp    = (const float*)d_in[1];
    const float* fc1_w = (const float*)d_in[2];
    const float* fc1_b = (const float*)d_in[3];
    const float* fc2_w = (const float*)d_in[4];
    const float* fc2_b = (const float*)d_in[5];
    const float* fc3_w = (const float*)d_in[6];
    const float* fc3_b = (const float*)d_in[7];

    hyper0_kernel<<<1, TBS>>>(fc1_w, fc1_b, fc2_w, fc2_b, fc3_w, fc3_b);
    f0_kernel<<<NBLK, TBS>>>(x, lp, fc1_w, fc1_b, fc2_w, fc2_b, fc3_w, fc3_b);
    f1_kernel<<<NBLK, TBS>>>(fc1_w, fc1_b, fc2_w, fc2_b, fc3_w, fc3_b);
    for (int it = 0; it < MAX_ITERS; it++)
        rk_kernel<<<NBLK, TBS>>>(2 + it, fc1_w, fc1_b, fc2_w, fc2_b, fc3_w, fc3_b);
    out_kernel<<<(BATCH + TBS - 1) / TBS, TBS>>>((float*)d_out);
}

// round 6
// speedup vs baseline: 1.0299x; 1.0299x over previous
#include <cuda_runtime.h>
#include <math.h>

#define BATCH 200000
#define HALF  (BATCH / 2)
#define TBS   256
#define NBLK  ((HALF + TBS - 1) / TBS)   // 391 blocks; 3/SM residency guaranteed
#define MAX_ITERS 16
#define RTOL 1e-5f
#define ATOL 1e-5f

// ---------------------------------------------------------------------------
// Device state
// ---------------------------------------------------------------------------
struct Ctl { float t, dt, last_t, h0, d1; int active, cur, accepted; };
__device__ Ctl    g_ctl;
__device__ __align__(16) float g_par[5][384];   // scalar layout: f4{W0,W1,b,wu}x64 + f2{U0,U1}x64
__device__ double g_part[2][NBLK];
__device__ int    g_bar_count;                  // zero-init; self-resetting
__device__ volatile int g_bar_gen;
__device__ float4 g_ic[2][5][BATCH];

__constant__ float c_ALPHA[5] = { 0.2f, 0.3f, 0.8f, (float)(8.0/9.0), 1.0f };

__device__ __forceinline__ float tanh_fast(float x) {
    float y;
    asm("tanh.approx.f32 %0, %1;" : "=f"(y) : "f"(x));
    return y;
}

// ---------------------------------------------------------------------------
// Grid-wide barrier (all NBLK blocks resident by construction)
// ---------------------------------------------------------------------------
__device__ __forceinline__ void grid_sync() {
    __threadfence();
    __syncthreads();
    if (threadIdx.x == 0) {
        int g = g_bar_gen;
        if (atomicAdd(&g_bar_count, 1) == (int)gridDim.x - 1) {
            g_bar_count = 0;
            __threadfence();
            g_bar_gen = g + 1;
        } else {
            while (g_bar_gen == g) __nanosleep(40);
        }
    }
    __syncthreads();
}

// ---------------------------------------------------------------------------
// RHS of the REVERSE ODE for TWO elements (R4 scalar math, shared-mem params)
// ---------------------------------------------------------------------------
__device__ __forceinline__ void rhs2(const float* __restrict__ sh,
                                     float az0, float az1, float bz0, float bz1,
                                     float& af0, float& af1, float& afl,
                                     float& bf0, float& bf1, float& bfl) {
    const float4* __restrict__ A  = reinterpret_cast<const float4*>(sh);
    const float2* __restrict__ Uv = reinterpret_cast<const float2*>(sh + 256);
    float aa0 = 0.f, aa1 = 0.f, atr = 0.f;
    float ba0 = 0.f, ba1 = 0.f, btr = 0.f;
    #pragma unroll 8
    for (int i = 0; i < 64; i++) {
        float4 a = A[i];
        float2 u = Uv[i];
        float pa = fmaf(az0, a.x, fmaf(az1, a.y, a.z));
        float pb = fmaf(bz0, a.x, fmaf(bz1, a.y, a.z));
        float ha = tanh_fast(pa);
        float hb = tanh_fast(pb);
        aa0 = fmaf(ha, u.x, aa0);
        aa1 = fmaf(ha, u.y, aa1);
        atr = fmaf(fmaf(-ha, ha, 1.0f), a.w, atr);
        ba0 = fmaf(hb, u.x, ba0);
        ba1 = fmaf(hb, u.y, ba1);
        btr = fmaf(fmaf(-hb, hb, 1.0f), a.w, btr);
    }
    af0 = -aa0 * (1.0f/64.0f);  af1 = -aa1 * (1.0f/64.0f);  afl = atr * (1.0f/64.0f);
    bf0 = -ba0 * (1.0f/64.0f);  bf1 = -ba1 * (1.0f/64.0f);  bfl = btr * (1.0f/64.0f);
}

// ---------------------------------------------------------------------------
// hypernet for one t, whole block cooperates; writes scalar layout to dst
// ---------------------------------------------------------------------------
__device__ void hyper_block(float t, float* dst,
                            const float* __restrict__ fc1_w, const float* __restrict__ fc1_b,
                            const float* __restrict__ fc2_w, const float* __restrict__ fc2_b,
                            const float* __restrict__ fc3_w, const float* __restrict__ fc3_b,
                            float* s1, float* s2, float* s3) {
    const int tid = threadIdx.x;
    if (tid < 64)
        s1[tid] = tanhf(fmaf(fc1_w[tid], t, fc1_b[tid]));
    __syncthreads();
    if (tid < 64) {
        float acc = fc2_b[tid];
        const float* row = fc2_w + tid * 64;
        #pragma unroll 8
        for (int k = 0; k < 64; k++) acc = fmaf(row[k], s1[k], acc);
        s2[tid] = tanhf(acc);
    }
    __syncthreads();
    for (int r = tid; r < 448; r += TBS) {
        float acc = fc3_b[r];
        const float* row = fc3_w + r * 64;
        #pragma unroll 8
        for (int k = 0; k < 64; k++) acc = fmaf(row[k], s2[k], acc);
        s3[r] = acc;
    }
    __syncthreads();
    if (tid < 64) {
        float W0 = s3[2*tid], W1 = s3[2*tid+1];
        float U0 = s3[128+2*tid], U1 = s3[128+2*tid+1];
        float G0 = s3[256+2*tid], G1 = s3[256+2*tid+1];
        float b  = s3[384+tid];
        U0 *= 1.0f / (1.0f + expf(-G0));
        U1 *= 1.0f / (1.0f + expf(-G1));
        float wu = W0 * U0 + W1 * U1;
        reinterpret_cast<float4*>(dst)[tid]       = make_float4(W0, W1, b, wu);
        reinterpret_cast<float2*>(dst + 256)[tid] = make_float2(U0, U1);
    }
    __syncthreads();
}

__device__ __forceinline__ double block_reduce(double v, double* sd) {
    int tid = threadIdx.x;
    sd[tid] = v;
    __syncthreads();
    for (int s = TBS / 2; s > 0; s >>= 1) {
        if (tid < s) sd[tid] += sd[tid + s];
        __syncthreads();
    }
    double r = sd[0];
    __syncthreads();
    return r;
}

// ---------------------------------------------------------------------------
// THE persistent kernel: init + dopri5 loop + output, one launch
// ---------------------------------------------------------------------------
__global__ __launch_bounds__(TBS, 3)
void solve_kernel(const float* __restrict__ x, const float* __restrict__ lp_in,
                  const float* __restrict__ fc1_w, const float* __restrict__ fc1_b,
                  const float* __restrict__ fc2_w, const float* __restrict__ fc2_b,
                  const float* __restrict__ fc3_w, const float* __restrict__ fc3_b,
                  float* __restrict__ out) {
    __shared__ __align__(16) float sp[5 * 384];
    __shared__ double sd[TBS];
    __shared__ float s1[64], s2[64], s3[448];
    __shared__ float sb[4];

    volatile Ctl* vc = &g_ctl;
    const int tid = threadIdx.x;
    const int gid = blockIdx.x * TBS + tid;
    const bool act_th = (gid < HALF);
    const int gA = gid, gB = gid + HALF;
    const bool isB0 = (blockIdx.x == 0);

    // ---- P0: params at t = 1 (block 0), everyone else waits -----------------
    if (isB0)
        hyper_block(1.0f, g_par[0], fc1_w, fc1_b, fc2_w, fc2_b, fc3_w, fc3_b, s1, s2, s3);
    grid_sync();

    // ---- P1: f0 + d0/d1 norms ----------------------------------------------
    for (int j = tid; j < 96; j += TBS)
        reinterpret_cast<float4*>(sp)[j] = __ldcg(reinterpret_cast<const float4*>(g_par[0]) + j);
    __syncthreads();

    float yA0=0.f, yA1=0.f, yAl=0.f, yB0=0.f, yB1=0.f, yBl=0.f;   // state (regs)
    float fA0=0.f, fA1=0.f, fAl=0.f, fB0=0.f, fB1=0.f, fBl=0.f;   // FSAL f (regs)
    {
        double n0 = 0.0, n1 = 0.0;
        if (act_th) {
            float2 xa = reinterpret_cast<const float2*>(x)[gA];
            float2 xb = reinterpret_cast<const float2*>(x)[gB];
            yA0 = xa.x; yA1 = xa.y; yAl = lp_in[gA];
            yB0 = xb.x; yB1 = xb.y; yBl = lp_in[gB];
            rhs2(sp, yA0, yA1, yB0, yB1, fA0, fA1, fAl, fB0, fB1, fBl);

            float sc0 = ATOL + RTOL * fabsf(yA0);
            float sc1 = ATOL + RTOL * fabsf(yA1);
            float scl = ATOL + RTOL * fabsf(yAl);
            float a = yA0/sc0, b = yA1/sc1, c = yAl/scl;
            n0 += (double)a*a + (double)b*b + (double)c*c;
            a = fA0/sc0; b = fA1/sc1; c = fAl/scl;
            n1 += (double)a*a + (double)b*b + (double)c*c;
            sc0 = ATOL + RTOL * fabsf(yB0);
            sc1 = ATOL + RTOL * fabsf(yB1);
            scl = ATOL + RTOL * fabsf(yBl);
            a = yB0/sc0; b = yB1/sc1; c = yBl/scl;
            n0 += (double)a*a + (double)b*b + (double)c*c;
            a = fB0/sc0; b = fB1/sc1; c = fBl/scl;
            n1 += (double)a*a + (double)b*b + (double)c*c;
        }
        double t0 = block_reduce(n0, sd);
        double t1 = block_reduce(n1, sd);
        if (tid == 0) { g_part[0][blockIdx.x] = t0; g_part[1][blockIdx.x] = t1; }
    }
    grid_sync();

    if (isB0) {
        double a0 = 0.0, a1 = 0.0;
        for (int i = tid; i < NBLK; i += TBS) {
            a0 += __ldcg(&g_part[0][i]);
            a1 += __ldcg(&g_part[1][i]);
        }
        double r0 = block_reduce(a0, sd);
        double r1 = block_reduce(a1, sd);
        if (tid == 0) {
            float d0 = (float)sqrt(r0);
            float d1 = (float)sqrt(r1);
            float h0 = (d0 < 1e-5f || d1 < 1e-5f) ? 1e-6f : 0.01f * d0 / d1;
            g_ctl.h0 = h0;  g_ctl.d1 = d1;
            sb[0] = h0;
        }
        __syncthreads();
        hyper_block(1.0f - sb[0], g_par[0],
                    fc1_w, fc1_b, fc2_w, fc2_b, fc3_w, fc3_b, s1, s2, s3);
    }
    grid_sync();

    // ---- P2: f1 + d2 norm ---------------------------------------------------
    for (int j = tid; j < 96; j += TBS)
        reinterpret_cast<float4*>(sp)[j] = __ldcg(reinterpret_cast<const float4*>(g_par[0]) + j);
    __syncthreads();
    {
        const float h0 = vc->h0;
        double n2 = 0.0;
        if (act_th) {
            float na0, na1, nal, nb0, nb1, nbl;
            rhs2(sp, fmaf(h0, fA0, yA0), fmaf(h0, fA1, yA1),
                     fmaf(h0, fB0, yB0), fmaf(h0, fB1, yB1),
                 na0, na1, nal, nb0, nb1, nbl);
            float sc0 = ATOL + RTOL * fabsf(yA0);
            float sc1 = ATOL + RTOL * fabsf(yA1);
            float scl = ATOL + RTOL * fabsf(yAl);
            float a = (na0 - fA0)/sc0, b = (na1 - fA1)/sc1, c = (nal - fAl)/scl;
            n2 += (double)a*a + (double)b*b + (double)c*c;
            sc0 = ATOL + RTOL * fabsf(yB0);
            sc1 = ATOL + RTOL * fabsf(yB1);
            scl = ATOL + RTOL * fabsf(yBl);
            a = (nb0 - fB0)/sc0; b = (nb1 - fB1)/sc1; c = (nbl - fBl)/scl;
            n2 += (double)a*a + (double)b*b + (double)c*c;
        }
        double t2 = block_reduce(n2, sd);
        if (tid == 0) g_part[0][blockIdx.x] = t2;
    }
    grid_sync();

    if (isB0) {
        double a0 = 0.0;
        for (int i = tid; i < NBLK; i += TBS) a0 += __ldcg(&g_part[0][i]);
        double tot = block_reduce(a0, sd);
        if (tid == 0) {
            float h0 = g_ctl.h0, d1 = g_ctl.d1;
            float d2 = (float)sqrt(tot) / h0;
            float h1 = (d1 <= 1e-15f && d2 <= 1e-15f)
                     ? fmaxf(1e-6f, h0 * 1e-3f)
                     : powf(0.01f / fmaxf(d1, d2), 0.2f);
            float dt = fminf(100.0f * h0, h1);
            g_ctl.t = 0.0f;  g_ctl.last_t = 0.0f;  g_ctl.dt = dt;
            g_ctl.active = 1;  g_ctl.cur = 0;  g_ctl.accepted = 0;
            sb[0] = dt;
        }
        __syncthreads();
        float dt = sb[0];
        #pragma unroll
        for (int i = 0; i < 5; i++)
            hyper_block(1.0f - dt * c_ALPHA[i], g_par[i],
                        fc1_w, fc1_b, fc2_w, fc2_b, fc3_w, fc3_b, s1, s2, s3);
    }
    grid_sync();

    // ---- dopri5 loop --------------------------------------------------------
    const float B1 = (float)(1.0/5.0);
    const float B20 = (float)(3.0/40.0), B21 = (float)(9.0/40.0);
    const float B30 = (float)(44.0/45.0), B31 = (float)(-56.0/15.0), B32 = (float)(32.0/9.0);
    const float B40 = (float)(19372.0/6561.0), B41 = (float)(-25360.0/2187.0),
                B42 = (float)(64448.0/6561.0), B43 = (float)(-212.0/729.0);
    const float B50 = (float)(9017.0/3168.0), B51 = (float)(-355.0/33.0),
                B52 = (float)(46732.0/5247.0), B53 = (float)(49.0/176.0),
                B54 = (float)(-5103.0/18656.0);
    const float CS[6] = { (float)(35.0/384.0), 0.0f, (float)(500.0/1113.0),
                          (float)(125.0/192.0), (float)(-2187.0/6784.0), (float)(11.0/84.0) };
    const float CE[7] = {
        (float)(35.0/384.0 - 1951.0/21600.0), 0.0f,
        (float)(500.0/1113.0 - 22642.0/50085.0),
        (float)(125.0/192.0 - 451.0/720.0),
        (float)(-2187.0/6784.0 + 12231.0/42400.0),
        (float)(11.0/84.0 - 649.0/6300.0),
        (float)(-1.0/60.0) };
    const float CM[7] = {
        (float)(6025192743.0/30085553152.0/2.0), 0.0f,
        (float)(51252292925.0/65400821598.0/2.0),
        (float)(-2691868925.0/45128329728.0/2.0),
        (float)(187940372067.0/1594534317056.0/2.0),
        (float)(-1776094331.0/19743644256.0/2.0),
        (float)(11237099.0/235043384.0/2.0) };

    for (int it = 0; it < MAX_ITERS; it++) {
        const float tcur = vc->t;
        const float dt   = vc->dt;
        const int   cur  = vc->cur;
        const int   nc   = cur ^ 1;
        const bool  pot_final = (tcur + dt >= 1.0f);

        for (int j = tid; j < 5 * 96; j += TBS)
            reinterpret_cast<float4*>(sp)[j] = __ldcg(reinterpret_cast<const float4*>(g_par) + j);
        __syncthreads();

        float nyA0=0,nyA1=0,nyAl=0, nyB0=0,nyB1=0,nyBl=0;
        float nfA0=0,nfA1=0,nfAl=0, nfB0=0,nfB1=0,nfBl=0;
        double esum = 0.0;

        if (act_th) {
            float k0A[7], k1A[7], klA[7], k0B[7], k1B[7], klB[7];
            k0A[0]=fA0; k1A[0]=fA1; klA[0]=fAl;
            k0B[0]=fB0; k1B[0]=fB1; klB[0]=fBl;

            rhs2(sp, fmaf(dt*B1, k0A[0], yA0), fmaf(dt*B1, k1A[0], yA1),
                     fmaf(dt*B1, k0B[0], yB0), fmaf(dt*B1, k1B[0], yB1),
                 k0A[1], k1A[1], klA[1], k0B[1], k1B[1], klB[1]);
            {
                float aA0 = fmaf(B21,k0A[1], B20*k0A[0]);
                float aA1 = fmaf(B21,k1A[1], B20*k1A[0]);
                float aB0 = fmaf(B21,k0B[1], B20*k0B[0]);
                float aB1 = fmaf(B21,k1B[1], B20*k1B[0]);
                rhs2(sp + 384, fmaf(dt,aA0,yA0), fmaf(dt,aA1,yA1),
                               fmaf(dt,aB0,yB0), fmaf(dt,aB1,yB1),
                     k0A[2], k1A[2], klA[2], k0B[2], k1B[2], klB[2]);
            }
            {
                float aA0 = fmaf(B32,k0A[2], fmaf(B31,k0A[1], B30*k0A[0]));
                float aA1 = fmaf(B32,k1A[2], fmaf(B31,k1A[1], B30*k1A[0]));
                float aB0 = fmaf(B32,k0B[2], fmaf(B31,k0B[1], B30*k0B[0]));
                float aB1 = fmaf(B32,k1B[2], fmaf(B31,k1B[1], B30*k1B[0]));
                rhs2(sp + 2*384, fmaf(dt,aA0,yA0), fmaf(dt,aA1,yA1),
                                 fmaf(dt,aB0,yB0), fmaf(dt,aB1,yB1),
                     k0A[3], k1A[3], klA[3], k0B[3], k1B[3], klB[3]);
            }
            {
                float aA0 = fmaf(B43,k0A[3], fmaf(B42,k0A[2], fmaf(B41,k0A[1], B40*k0A[0])));
                float aA1 = fmaf(B43,k1A[3], fmaf(B42,k1A[2], fmaf(B41,k1A[1], B40*k1A[0])));
                float aB0 = fmaf(B43,k0B[3], fmaf(B42,k0B[2], fmaf(B41,k0B[1], B40*k0B[0])));
                float aB1 = fmaf(B43,k1B[3], fmaf(B42,k1B[2], fmaf(B41,k1B[1], B40*k1B[0])));
                rhs2(sp + 3*384, fmaf(dt,aA0,yA0), fmaf(dt,aA1,yA1),
                                 fmaf(dt,aB0,yB0), fmaf(dt,aB1,yB1),
                     k0A[4], k1A[4], klA[4], k0B[4], k1B[4], klB[4]);
            }
            {
                float aA0 = fmaf(B54,k0A[4], fmaf(B53,k0A[3], fmaf(B52,k0A[2], fmaf(B51,k0A[1], B50*k0A[0]))));
                float aA1 = fmaf(B54,k1A[4], fmaf(B53,k1A[3], fmaf(B52,k1A[2], fmaf(B51,k1A[1], B50*k1A[0]))));
                float aB0 = fmaf(B54,k0B[4], fmaf(B53,k0B[3], fmaf(B52,k0B[2], fmaf(B51,k0B[1], B50*k0B[0]))));
                float aB1 = fmaf(B54,k1B[4], fmaf(B53,k1B[3], fmaf(B52,k1B[2], fmaf(B51,k1B[1], B50*k1B[0]))));
                rhs2(sp + 4*384, fmaf(dt,aA0,yA0), fmaf(dt,aA1,yA1),
                                 fmaf(dt,aB0,yB0), fmaf(dt,aB1,yB1),
                     k0A[5], k1A[5], klA[5], k0B[5], k1B[5], klB[5]);
            }

            float sA0=0,sA1=0,sAl=0, sB0=0,sB1=0,sBl=0;
            #pragma unroll
            for (int j = 0; j < 6; j++) {
                sA0 = fmaf(CS[j], k0A[j], sA0);  sA1 = fmaf(CS[j], k1A[j], sA1);
                sAl = fmaf(CS[j], klA[j], sAl);
                sB0 = fmaf(CS[j], k0B[j], sB0);  sB1 = fmaf(CS[j], k1B[j], sB1);
                sBl = fmaf(CS[j], klB[j], sBl);
            }
            nyA0 = fmaf(dt,sA0,yA0); nyA1 = fmaf(dt,sA1,yA1); nyAl = fmaf(dt,sAl,yAl);
            nyB0 = fmaf(dt,sB0,yB0); nyB1 = fmaf(dt,sB1,yB1); nyBl = fmaf(dt,sBl,yBl);

            rhs2(sp + 4*384, nyA0, nyA1, nyB0, nyB1,
                 k0A[6], k1A[6], klA[6], k0B[6], k1B[6], klB[6]);
            nfA0=k0A[6]; nfA1=k1A[6]; nfAl=klA[6];
            nfB0=k0B[6]; nfB1=k1B[6]; nfBl=klB[6];

            float eA0=0,eA1=0,eAl=0, eB0=0,eB1=0,eBl=0;
            float mA0=0,mA1=0,mAl=0, mB0=0,mB1=0,mBl=0;
            #pragma unroll
            for (int j = 0; j < 7; j++) {
                eA0 = fmaf(CE[j],k0A[j],eA0);  eA1 = fmaf(CE[j],k1A[j],eA1);
                eAl = fmaf(CE[j],klA[j],eAl);
                eB0 = fmaf(CE[j],k0B[j],eB0);  eB1 = fmaf(CE[j],k1B[j],eB1);
                eBl = fmaf(CE[j],klB[j],eBl);
                mA0 = fmaf(CM[j],k0A[j],mA0);  mA1 = fmaf(CM[j],k1A[j],mA1);
                mAl = fmaf(CM[j],klA[j],mAl);
                mB0 = fmaf(CM[j],k0B[j],mB0);  mB1 = fmaf(CM[j],k1B[j],mB1);
                mBl = fmaf(CM[j],klB[j],mBl);
            }

            {
                float t0 = ATOL + RTOL * fmaxf(fabsf(yA0), fabsf(nyA0));
                float t1 = ATOL + RTOL * fmaxf(fabsf(yA1), fabsf(nyA1));
                float tl = ATOL + RTOL * fmaxf(fabsf(yAl), fabsf(nyAl));
                float r0 = dt*eA0/t0, r1 = dt*eA1/t1, rl = dt*eAl/tl;
                esum += (double)r0*r0 + (double)r1*r1 + (double)rl*rl;
                t0 = ATOL + RTOL * fmaxf(fabsf(yB0), fabsf(nyB0));
                t1 = ATOL + RTOL * fmaxf(fabsf(yB1), fabsf(nyB1));
                tl = ATOL + RTOL * fmaxf(fabsf(yBl), fabsf(nyBl));
                r0 = dt*eB0/t0; r1 = dt*eB1/t1; rl = dt*eBl/tl;
                esum += (double)r0*r0 + (double)r1*r1 + (double)rl*rl;
            }

            if (pot_final) {
                // interp coefficients, only when this step can be the final one
                float ym[6] = { fmaf(dt,mA0,yA0), fmaf(dt,mA1,yA1), fmaf(dt,mAl,yAl),
                                fmaf(dt,mB0,yB0), fmaf(dt,mB1,yB1), fmaf(dt,mBl,yBl) };
                float y0v[6] = { yA0, yA1, yAl, yB0, yB1, yBl };
                float y1v[6] = { nyA0, nyA1, nyAl, nyB0, nyB1, nyBl };
                float d0v[6] = { dt*k0A[0], dt*k1A[0], dt*klA[0], dt*k0B[0], dt*k1B[0], dt*klB[0] };
                float d1v[6] = { dt*k0A[6], dt*k1A[6], dt*klA[6], dt*k0B[6], dt*k1B[6], dt*klB[6] };
                float Av[6], Bv[6], Cv[6];
                #pragma unroll
                for (int c = 0; c < 6; c++) {
                    Av[c] = -2.f*d0v[c] + 2.f*d1v[c] - 8.f*y0v[c] - 8.f*y1v[c] + 16.f*ym[c];
                    Bv[c] =  5.f*d0v[c] - 3.f*d1v[c] + 18.f*y0v[c] + 14.f*y1v[c] - 32.f*ym[c];
                    Cv[c] = -4.f*d0v[c] + d1v[c] - 11.f*y0v[c] - 5.f*y1v[c] + 16.f*ym[c];
                }
                g_ic[nc][0][gA] = make_float4(Av[0], Av[1], Av[2], 0.f);
                g_ic[nc][1][gA] = make_float4(Bv[0], Bv[1], Bv[2], 0.f);
                g_ic[nc][2][gA] = make_float4(Cv[0], Cv[1], Cv[2], 0.f);
                g_ic[nc][3][gA] = make_float4(d0v[0], d0v[1], d0v[2], 0.f);
                g_ic[nc][4][gA] = make_float4(y0v[0], y0v[1], y0v[2], 0.f);
                g_ic[nc][0][gB] = make_float4(Av[3], Av[4], Av[5], 0.f);
                g_ic[nc][1][gB] = make_float4(Bv[3], Bv[4], Bv[5], 0.f);
                g_ic[nc][2][gB] = make_float4(Cv[3], Cv[4], Cv[5], 0.f);
                g_ic[nc][3][gB] = make_float4(d0v[3], d0v[4], d0v[5], 0.f);
                g_ic[nc][4][gB] = make_float4(y0v[3], y0v[4], y0v[5], 0.f);
            }
        }

        double tot = block_reduce(esum, sd);
        if (tid == 0) g_part[0][blockIdx.x] = tot;
        grid_sync();

        if (isB0) {
            double a0 = 0.0;
            for (int i = tid; i < NBLK; i += TBS) a0 += __ldcg(&g_part[0][i]);
            double t2 = block_reduce(a0, sd);
            if (tid == 0) {
                float r = (float)sqrt(t2 / (3.0 * (double)BATCH));
                float dtc = g_ctl.dt;
                float dfac = (r < 1.0f) ? 1.0f : 0.2f;
                float factor = fminf(10.0f, fmaxf(powf(r, -0.2f) * 0.9f, dfac));
                float dt_new = (r == 0.0f) ? dtc * 10.0f : dtc * factor;
                int acc = (r <= 1.0f);
                if (acc) {
                    g_ctl.last_t = g_ctl.t;
                    g_ctl.t += dtc;
                    g_ctl.cur ^= 1;
                }
                g_ctl.accepted = acc;
                g_ctl.dt = dt_new;
                int act = (g_ctl.t < 1.0f);
                g_ctl.active = act;
                sb[0] = g_ctl.t;  sb[1] = dt_new;  sb[2] = (float)act;
            }
            __syncthreads();
            if (sb[2] != 0.0f) {
                float tn = sb[0], dtn = sb[1];
                #pragma unroll
                for (int i = 0; i < 5; i++)
                    hyper_block(1.0f - fmaf(dtn, c_ALPHA[i], tn), g_par[i],
                                fc1_w, fc1_b, fc2_w, fc2_b, fc3_w, fc3_b, s1, s2, s3);
            }
        }
        grid_sync();

        if (vc->accepted && act_th) {
            yA0=nyA0; yA1=nyA1; yAl=nyAl;  yB0=nyB0; yB1=nyB1; yBl=nyBl;
            fA0=nfA0; fA1=nfA1; fAl=nfAl;  fB0=nfB0; fB1=nfB1; fBl=nfBl;
        }
        if (!vc->active) break;
    }

    // ---- output -------------------------------------------------------------
    if (act_th) {
        const int cur = vc->cur;
        const float xr = (1.0f - vc->last_t) / (vc->t - vc->last_t);
        #pragma unroll
        for (int e = 0; e < 2; e++) {
            int g = e ? gB : gA;
            float4 A  = g_ic[cur][0][g];
            float4 Bc = g_ic[cur][1][g];
            float4 C  = g_ic[cur][2][g];
            float4 D  = g_ic[cur][3][g];
            float4 E  = g_ic[cur][4][g];
            float z0 = fmaf(fmaf(fmaf(fmaf(A.x, xr, Bc.x), xr, C.x), xr, D.x), xr, E.x);
            float z1 = fmaf(fmaf(fmaf(fmaf(A.y, xr, Bc.y), xr, C.y), xr, D.y), xr, E.y);
            float lp = fmaf(fmaf(fmaf(fmaf(A.z, xr, Bc.z), xr, C.z), xr, D.z), xr, E.z);
            reinterpret_cast<float2*>(out)[g] = make_float2(z0, z1);
            out[2 * BATCH + g] = lp;
        }
    }
}

// ---------------------------------------------------------------------------
extern "C" void kernel_launch(void* const* d_in, const int* in_sizes, int n_in,
                              void* d_out, int out_size) {
    const float* x     = (const float*)d_in[0];
    const float* lp    = (const float*)d_in[1];
    const float* fc1_w = (const float*)d_in[2];
    const float* fc1_b = (const float*)d_in[3];
    const float* fc2_w = (const float*)d_in[4];
    const float* fc2_b = (const float*)d_in[5];
    const float* fc3_w = (const float*)d_in[6];
    const float* fc3_b = (const float*)d_in[7];

    solve_kernel<<<NBLK, TBS>>>(x, lp, fc1_w, fc1_b, fc2_w, fc2_b,
                                fc3_w, fc3_b, (float*)d_out);
}

// round 7
// speedup vs baseline: 1.6751x; 1.6266x over previous
#include <cuda_runtime.h>
#include <math.h>

#define BATCH 200000
#define TBS 256
#define NBLK ((BATCH + TBS - 1) / TBS)   // 782
#define MAX_ITERS 10
#define RTOL 1e-5f
#define ATOL 1e-5f

// ---------------------------------------------------------------------------
// Device state
// ---------------------------------------------------------------------------
struct Ctl { float t, dt, last_t, h0, d1; int active, cur; };
__device__ Ctl g_ctl;
__device__ __align__(16) float g_par[5][384];
__device__ double g_part[2][NBLK];
__device__ int    g_cnt[MAX_ITERS + 4];        // zero-init; self-resetting

__device__ float2 g_yz[2][BATCH];
__device__ float  g_yl[2][BATCH];
__device__ float2 g_fz[2][BATCH];
__device__ float  g_fl[2][BATCH];
__device__ float4 g_ic[2][5][BATCH];

__constant__ float c_ALPHA[5] = { 0.2f, 0.3f, 0.8f, (float)(8.0/9.0), 1.0f };

__device__ __forceinline__ float tanh_fast(float x) {
    float y;
    asm("tanh.approx.f32 %0, %1;" : "=f"(y) : "f"(x));
    return y;
}

// ---------------------------------------------------------------------------
// RHS of the REVERSE ODE, ONE element (bitwise-identical per-element math to R4)
// ---------------------------------------------------------------------------
__device__ __forceinline__ void rhs1(const float* __restrict__ sh,
                                     float z0, float z1,
                                     float& f0, float& f1, float& fl) {
    const float4* __restrict__ A  = reinterpret_cast<const float4*>(sh);
    const float2* __restrict__ Uv = reinterpret_cast<const float2*>(sh + 256);
    float a0 = 0.f, a1 = 0.f, tr = 0.f;
    #pragma unroll 16
    for (int i = 0; i < 64; i++) {
        float4 a = A[i];
        float2 u = Uv[i];
        float pre = fmaf(z0, a.x, fmaf(z1, a.y, a.z));
        float h = tanh_fast(pre);
        a0 = fmaf(h, u.x, a0);
        a1 = fmaf(h, u.y, a1);
        tr = fmaf(fmaf(-h, h, 1.0f), a.w, tr);
    }
    f0 = -a0 * (1.0f/64.0f);
    f1 = -a1 * (1.0f/64.0f);
    fl =  tr * (1.0f/64.0f);
}

__device__ __forceinline__ double block_reduce(double v, double* sd) {
    int tid = threadIdx.x;
    sd[tid] = v;
    __syncthreads();
    for (int s = TBS / 2; s > 0; s >>= 1) {
        if (tid < s) sd[tid] += sd[tid + s];
        __syncthreads();
    }
    double r = sd[0];
    __syncthreads();
    return r;
}

__device__ __forceinline__ bool elect_last_block(int slot) {
    __threadfence();
    __shared__ int isLast;
    if (threadIdx.x == 0) {
        int c = atomicAdd(&g_cnt[slot], 1);
        isLast = (c == (int)gridDim.x - 1);
    }
    __syncthreads();
    return isLast != 0;
}

// ---------------------------------------------------------------------------
// hypernet: mode 0: s=0 ; mode 1: s=g_ctl.h0 ; mode 2: s=t+dt*alpha[m]
// ---------------------------------------------------------------------------
__global__ __launch_bounds__(448)
void hyper_kernel(const float* __restrict__ fc1_w, const float* __restrict__ fc1_b,
                  const float* __restrict__ fc2_w, const float* __restrict__ fc2_b,
                  const float* __restrict__ fc3_w, const float* __restrict__ fc3_b,
                  int mode) {
    if (mode == 2 && !g_ctl.active) return;
    __shared__ float p1[64];
    __shared__ float p2[64];
    __shared__ float p3[448];

    const int m = blockIdx.x;
    const int tid = threadIdx.x;
    float s = (mode == 0) ? 0.0f
            : (mode == 1) ? g_ctl.h0
            : fmaf(g_ctl.dt, c_ALPHA[m], g_ctl.t);
    const float t = 1.0f - s;

    if (tid < 64)
        p1[tid] = tanhf(fmaf(fc1_w[tid], t, fc1_b[tid]));
    __syncthreads();

    if (tid < 64) {
        float acc = fc2_b[tid];
        const float* row = fc2_w + tid * 64;
        #pragma unroll 8
        for (int k = 0; k < 64; k++) acc = fmaf(row[k], p1[k], acc);
        p2[tid] = tanhf(acc);
    }
    __syncthreads();

    {
        float acc = fc3_b[tid];
        const float* row = fc3_w + tid * 64;
        #pragma unroll 8
        for (int k = 0; k < 64; k++) acc = fmaf(row[k], p2[k], acc);
        p3[tid] = acc;
    }
    __syncthreads();

    if (tid < 64) {
        float W0 = p3[2 * tid + 0];
        float W1 = p3[2 * tid + 1];
        float U0 = p3[128 + 2 * tid + 0];
        float U1 = p3[128 + 2 * tid + 1];
        float G0 = p3[256 + 2 * tid + 0];
        float G1 = p3[256 + 2 * tid + 1];
        float b  = p3[384 + tid];
        U0 *= 1.0f / (1.0f + expf(-G0));
        U1 *= 1.0f / (1.0f + expf(-G1));
        float wu = W0 * U0 + W1 * U1;
        float* base = g_par[m];
        reinterpret_cast<float4*>(base)[tid]       = make_float4(W0, W1, b, wu);
        reinterpret_cast<float2*>(base + 256)[tid] = make_float2(U0, U1);
    }
}

// ---------------------------------------------------------------------------
// f0: f(y0,0) + d0,d1 norms; tail: h0
// ---------------------------------------------------------------------------
__global__ __launch_bounds__(TBS)
void f0_kernel(const float* __restrict__ x, const float* __restrict__ lp_in) {
    __shared__ __align__(16) float shp[384];
    __shared__ double sd[TBS];
    for (int j = threadIdx.x; j < 96; j += TBS)
        reinterpret_cast<float4*>(shp)[j] = reinterpret_cast<const float4*>(g_par[0])[j];
    __syncthreads();

    const int gid = blockIdx.x * TBS + threadIdx.x;
    double n0 = 0.0, n1 = 0.0;
    if (gid < BATCH) {
        float2 ya = reinterpret_cast<const float2*>(x)[gid];
        float  la = lp_in[gid];
        float f0, f1, fl;
        rhs1(shp, ya.x, ya.y, f0, f1, fl);
        g_yz[0][gid] = ya;  g_yl[0][gid] = la;
        g_fz[0][gid] = make_float2(f0, f1);  g_fl[0][gid] = fl;

        float sc0 = ATOL + RTOL * fabsf(ya.x);
        float sc1 = ATOL + RTOL * fabsf(ya.y);
        float scl = ATOL + RTOL * fabsf(la);
        float a = ya.x/sc0, b = ya.y/sc1, c = la/scl;
        n0 += (double)a*a + (double)b*b + (double)c*c;
        a = f0/sc0; b = f1/sc1; c = fl/scl;
        n1 += (double)a*a + (double)b*b + (double)c*c;
    }
    double t0 = block_reduce(n0, sd);
    double t1 = block_reduce(n1, sd);
    if (threadIdx.x == 0) { g_part[0][blockIdx.x] = t0; g_part[1][blockIdx.x] = t1; }

    if (elect_last_block(0)) {
        double a0 = 0.0, a1 = 0.0;
        for (int i = threadIdx.x; i < NBLK; i += TBS) { a0 += g_part[0][i]; a1 += g_part[1][i]; }
        double r0 = block_reduce(a0, sd);
        double r1 = block_reduce(a1, sd);
        if (threadIdx.x == 0) {
            float d0 = (float)sqrt(r0);
            float d1 = (float)sqrt(r1);
            float h0 = (d0 < 1e-5f || d1 < 1e-5f) ? 1e-6f : 0.01f * d0 / d1;
            g_ctl.h0 = h0;
            g_ctl.d1 = d1;
            g_cnt[0] = 0;
        }
    }
}

// ---------------------------------------------------------------------------
// f1: f(y0+h0*f0, h0) + d2 norm; tail: initial dt + ctl init
// ---------------------------------------------------------------------------
__global__ __launch_bounds__(TBS)
void f1_kernel() {
    __shared__ __align__(16) float shp[384];
    __shared__ double sd[TBS];
    for (int j = threadIdx.x; j < 96; j += TBS)
        reinterpret_cast<float4*>(shp)[j] = reinterpret_cast<const float4*>(g_par[0])[j];
    __syncthreads();

    const int gid = blockIdx.x * TBS + threadIdx.x;
    const float h0 = g_ctl.h0;
    double n2 = 0.0;
    if (gid < BATCH) {
        float2 ya = g_yz[0][gid];  float la = g_yl[0][gid];
        float2 fa = g_fz[0][gid];  float fla = g_fl[0][gid];
        float na0, na1, nal;
        rhs1(shp, fmaf(h0, fa.x, ya.x), fmaf(h0, fa.y, ya.y), na0, na1, nal);
        float sc0 = ATOL + RTOL * fabsf(ya.x);
        float sc1 = ATOL + RTOL * fabsf(ya.y);
        float scl = ATOL + RTOL * fabsf(la);
        float a = (na0 - fa.x)/sc0, b = (na1 - fa.y)/sc1, c = (nal - fla)/scl;
        n2 += (double)a*a + (double)b*b + (double)c*c;
    }
    double t2 = block_reduce(n2, sd);
    if (threadIdx.x == 0) g_part[0][blockIdx.x] = t2;

    if (elect_last_block(1)) {
        double a0 = 0.0;
        for (int i = threadIdx.x; i < NBLK; i += TBS) a0 += g_part[0][i];
        double tot = block_reduce(a0, sd);
        if (threadIdx.x == 0) {
            float d1 = g_ctl.d1;
            float d2 = (float)sqrt(tot) / h0;
            float h1 = (d1 <= 1e-15f && d2 <= 1e-15f)
                     ? fmaxf(1e-6f, h0 * 1e-3f)
                     : powf(0.01f / fmaxf(d1, d2), 0.2f);
            float dt = fminf(100.0f * h0, h1);
            g_ctl.t = 0.0f;  g_ctl.last_t = 0.0f;  g_ctl.dt = dt;
            g_ctl.active = 1;  g_ctl.cur = 0;
            g_cnt[1] = 0;
        }
    }
}

// ---------------------------------------------------------------------------
// rk: one dopri5 step, ONE element/thread, controller in last block
// ---------------------------------------------------------------------------
__global__ __launch_bounds__(TBS, 4)
void rk_kernel(int slot) {
    if (!g_ctl.active) return;
    __shared__ __align__(16) float shp[5 * 384];
    __shared__ double sd[TBS];
    for (int j = threadIdx.x; j < 5 * 96; j += TBS)
        reinterpret_cast<float4*>(shp)[j] = reinterpret_cast<const float4*>(g_par)[j];
    __syncthreads();

    const float B1 = (float)(1.0/5.0);
    const float B20 = (float)(3.0/40.0), B21 = (float)(9.0/40.0);
    const float B30 = (float)(44.0/45.0), B31 = (float)(-56.0/15.0), B32 = (float)(32.0/9.0);
    const float B40 = (float)(19372.0/6561.0), B41 = (float)(-25360.0/2187.0),
                B42 = (float)(64448.0/6561.0), B43 = (float)(-212.0/729.0);
    const float B50 = (float)(9017.0/3168.0), B51 = (float)(-355.0/33.0),
                B52 = (float)(46732.0/5247.0), B53 = (float)(49.0/176.0),
                B54 = (float)(-5103.0/18656.0);
    const float CS[6] = { (float)(35.0/384.0), 0.0f, (float)(500.0/1113.0),
                          (float)(125.0/192.0), (float)(-2187.0/6784.0), (float)(11.0/84.0) };
    const float CE[7] = {
        (float)(35.0/384.0 - 1951.0/21600.0), 0.0f,
        (float)(500.0/1113.0 - 22642.0/50085.0),
        (float)(125.0/192.0 - 451.0/720.0),
        (float)(-2187.0/6784.0 + 12231.0/42400.0),
        (float)(11.0/84.0 - 649.0/6300.0),
        (float)(-1.0/60.0) };
    const float CM[7] = {
        (float)(6025192743.0/30085553152.0/2.0), 0.0f,
        (float)(51252292925.0/65400821598.0/2.0),
        (float)(-2691868925.0/45128329728.0/2.0),
        (float)(187940372067.0/1594534317056.0/2.0),
        (float)(-1776094331.0/19743644256.0/2.0),
        (float)(11237099.0/235043384.0/2.0) };

    const int gid = blockIdx.x * TBS + threadIdx.x;
    const int cur = g_ctl.cur;
    const int nc = cur ^ 1;
    const float dt = g_ctl.dt;
    const bool pot_final = (g_ctl.t + dt >= 1.0f);
    double esum = 0.0;

    if (gid < BATCH) {
        float2 yz = g_yz[cur][gid];  float yl = g_yl[cur][gid];
        float2 fz = g_fz[cur][gid];  float fl = g_fl[cur][gid];

        float k0[7], k1[7], kl[7];
        k0[0] = fz.x; k1[0] = fz.y; kl[0] = fl;

        rhs1(shp, fmaf(dt*B1, k0[0], yz.x), fmaf(dt*B1, k1[0], yz.y),
             k0[1], k1[1], kl[1]);
        {
            float a0 = fmaf(B21,k0[1], B20*k0[0]);
            float a1 = fmaf(B21,k1[1], B20*k1[0]);
            rhs1(shp + 384, fmaf(dt,a0,yz.x), fmaf(dt,a1,yz.y),
                 k0[2], k1[2], kl[2]);
        }
        {
            float a0 = fmaf(B32,k0[2], fmaf(B31,k0[1], B30*k0[0]));
            float a1 = fmaf(B32,k1[2], fmaf(B31,k1[1], B30*k1[0]));
            rhs1(shp + 2*384, fmaf(dt,a0,yz.x), fmaf(dt,a1,yz.y),
                 k0[3], k1[3], kl[3]);
        }
        {
            float a0 = fmaf(B43,k0[3], fmaf(B42,k0[2], fmaf(B41,k0[1], B40*k0[0])));
            float a1 = fmaf(B43,k1[3], fmaf(B42,k1[2], fmaf(B41,k1[1], B40*k1[0])));
            rhs1(shp + 3*384, fmaf(dt,a0,yz.x), fmaf(dt,a1,yz.y),
                 k0[4], k1[4], kl[4]);
        }
        {
            float a0 = fmaf(B54,k0[4], fmaf(B53,k0[3], fmaf(B52,k0[2], fmaf(B51,k0[1], B50*k0[0]))));
            float a1 = fmaf(B54,k1[4], fmaf(B53,k1[3], fmaf(B52,k1[2], fmaf(B51,k1[1], B50*k1[0]))));
            rhs1(shp + 4*384, fmaf(dt,a0,yz.x), fmaf(dt,a1,yz.y),
                 k0[5], k1[5], kl[5]);
        }

        float s0=0.f, s1=0.f, sl=0.f;
        #pragma unroll
        for (int j = 0; j < 6; j++) {
            s0 = fmaf(CS[j], k0[j], s0);
            s1 = fmaf(CS[j], k1[j], s1);
            sl = fmaf(CS[j], kl[j], sl);
        }
        float ny0 = fmaf(dt,s0,yz.x);
        float ny1 = fmaf(dt,s1,yz.y);
        float nyl = fmaf(dt,sl,yl);

        rhs1(shp + 4*384, ny0, ny1, k0[6], k1[6], kl[6]);

        float e0=0.f,e1=0.f,el=0.f, m0=0.f,m1=0.f,ml=0.f;
        #pragma unroll
        for (int j = 0; j < 7; j++) {
            e0 = fmaf(CE[j],k0[j],e0);  e1 = fmaf(CE[j],k1[j],e1);
            el = fmaf(CE[j],kl[j],el);
            m0 = fmaf(CM[j],k0[j],m0);  m1 = fmaf(CM[j],k1[j],m1);
            ml = fmaf(CM[j],kl[j],ml);
        }

        {
            float t0 = ATOL + RTOL * fmaxf(fabsf(yz.x), fabsf(ny0));
            float t1 = ATOL + RTOL * fmaxf(fabsf(yz.y), fabsf(ny1));
            float tl = ATOL + RTOL * fmaxf(fabsf(yl),   fabsf(nyl));
            float r0 = dt*e0/t0, r1 = dt*e1/t1, rl = dt*el/tl;
            esum = (double)r0*r0 + (double)r1*r1 + (double)rl*rl;
        }

        g_yz[nc][gid] = make_float2(ny0, ny1);  g_yl[nc][gid] = nyl;
        g_fz[nc][gid] = make_float2(k0[6], k1[6]);  g_fl[nc][gid] = kl[6];

        if (pot_final) {
            float ym0 = fmaf(dt,m0,yz.x), ym1 = fmaf(dt,m1,yz.y), yml = fmaf(dt,ml,yl);
            float d00 = dt*k0[0], d01 = dt*k1[0], d0l = dt*kl[0];
            float d10 = dt*k0[6], d11 = dt*k1[6], d1l = dt*kl[6];
            float A0 = -2.f*d00 + 2.f*d10 - 8.f*yz.x - 8.f*ny0 + 16.f*ym0;
            float A1 = -2.f*d01 + 2.f*d11 - 8.f*yz.y - 8.f*ny1 + 16.f*ym1;
            float Al = -2.f*d0l + 2.f*d1l - 8.f*yl   - 8.f*nyl + 16.f*yml;
            float B0v =  5.f*d00 - 3.f*d10 + 18.f*yz.x + 14.f*ny0 - 32.f*ym0;
            float B1v =  5.f*d01 - 3.f*d11 + 18.f*yz.y + 14.f*ny1 - 32.f*ym1;
            float Blv =  5.f*d0l - 3.f*d1l + 18.f*yl   + 14.f*nyl - 32.f*yml;
            float C0 = -4.f*d00 + d10 - 11.f*yz.x - 5.f*ny0 + 16.f*ym0;
            float C1 = -4.f*d01 + d11 - 11.f*yz.y - 5.f*ny1 + 16.f*ym1;
            float Cl = -4.f*d0l + d1l - 11.f*yl   - 5.f*nyl + 16.f*yml;
            g_ic[nc][0][gid] = make_float4(A0, A1, Al, 0.f);
            g_ic[nc][1][gid] = make_float4(B0v, B1v, Blv, 0.f);
            g_ic[nc][2][gid] = make_float4(C0, C1, Cl, 0.f);
            g_ic[nc][3][gid] = make_float4(d00, d01, d0l, 0.f);
            g_ic[nc][4][gid] = make_float4(yz.x, yz.y, yl, 0.f);
        }
    }

    double tot = block_reduce(esum, sd);
    if (threadIdx.x == 0) g_part[0][blockIdx.x] = tot;

    if (elect_last_block(slot)) {
        double a0 = 0.0;
        for (int i = threadIdx.x; i < NBLK; i += TBS) a0 += g_part[0][i];
        double t2 = block_reduce(a0, sd);
        if (threadIdx.x == 0) {
            float r = (float)sqrt(t2 / (3.0 * (double)BATCH));
            float dtc = g_ctl.dt;
            float dfac = (r < 1.0f) ? 1.0f : 0.2f;
            float factor = fminf(10.0f, fmaxf(powf(r, -0.2f) * 0.9f, dfac));
            float dt_new = (r == 0.0f) ? dtc * 10.0f : dtc * factor;
            if (r <= 1.0f) {
                g_ctl.last_t = g_ctl.t;
                g_ctl.t += dtc;
                g_ctl.cur ^= 1;
            }
            g_ctl.dt = dt_new;
            g_ctl.active = (g_ctl.t < 1.0f);
            g_cnt[slot] = 0;
        }
    }
}

// ---------------------------------------------------------------------------
// output: polyval of last accepted step's quartic
// ---------------------------------------------------------------------------
__global__ __launch_bounds__(TBS)
void out_kernel(float* __restrict__ out) {
    int gid = blockIdx.x * TBS + threadIdx.x;
    if (gid >= BATCH) return;
    const int cur = g_ctl.cur;
    const float xr = (1.0f - g_ctl.last_t) / (g_ctl.t - g_ctl.last_t);
    float4 A  = g_ic[cur][0][gid];
    float4 Bc = g_ic[cur][1][gid];
    float4 C  = g_ic[cur][2][gid];
    float4 D  = g_ic[cur][3][gid];
    float4 E  = g_ic[cur][4][gid];
    float z0 = fmaf(fmaf(fmaf(fmaf(A.x, xr, Bc.x), xr, C.x), xr, D.x), xr, E.x);
    float z1 = fmaf(fmaf(fmaf(fmaf(A.y, xr, Bc.y), xr, C.y), xr, D.y), xr, E.y);
    float lp = fmaf(fmaf(fmaf(fmaf(A.z, xr, Bc.z), xr, C.z), xr, D.z), xr, E.z);
    reinterpret_cast<float2*>(out)[gid] = make_float2(z0, z1);
    out[2 * BATCH + gid] = lp;
}

// ---------------------------------------------------------------------------
extern "C" void kernel_launch(void* const* d_in, const int* in_sizes, int n_in,
                              void* d_out, int out_size) {
    const float* x     = (const float*)d_in[0];
    const float* lp    = (const float*)d_in[1];
    const float* fc1_w = (const float*)d_in[2];
    const float* fc1_b = (const float*)d_in[3];
    const float* fc2_w = (const float*)d_in[4];
    const float* fc2_b = (const float*)d_in[5];
    const float* fc3_w = (const float*)d_in[6];
    const float* fc3_b = (const float*)d_in[7];

    hyper_kernel<<<1, 448>>>(fc1_w, fc1_b, fc2_w, fc2_b, fc3_w, fc3_b, 0);
    f0_kernel<<<NBLK, TBS>>>(x, lp);
    hyper_kernel<<<1, 448>>>(fc1_w, fc1_b, fc2_w, fc2_b, fc3_w, fc3_b, 1);
    f1_kernel<<<NBLK, TBS>>>();

    for (int it = 0; it < MAX_ITERS; it++) {
        hyper_kernel<<<5, 448>>>(fc1_w, fc1_b, fc2_w, fc2_b, fc3_w, fc3_b, 2);
        rk_kernel<<<NBLK, TBS>>>(2 + it);
    }
    out_kernel<<<NBLK, TBS>>>((float*)d_out);
}